// round 2
// baseline (speedup 1.0000x reference)
#include <cuda_runtime.h>
#include <cuda_fp16.h>
#include <cstdint>

// Problem constants
#define E_      8
#define D_      64
#define H_      512
#define B_      32768
#define IN_RAW  67
#define IN_PAD  128          // layer-1 K padded to 128 (zeros) for uniform K-chunking
#define BM      64           // batch rows per CTA
#define HSTR    520          // h-tile row stride (halves): conflict-free LDS
#define WSTR    72           // weight-tile row stride (halves): conflict-free LDS
#define THREADS 256
#define SMEM_BYTES ((2*BM*HSTR + 2*256*WSTR) * 2)   // 206,848 B

// Scratch (allocation-free rule: __device__ globals)
__device__ float  g_dyn[(size_t)E_ * B_ * D_];         // 64 MB: per-expert dyn
__device__ __half g_w1[E_ * H_ * IN_PAD];
__device__ __half g_w2[(size_t)E_ * H_ * H_];
__device__ __half g_w3[(size_t)E_ * H_ * H_];
__device__ __half g_w4[E_ * D_ * H_];

// ---------------- helpers ----------------
__device__ __forceinline__ void cp16(void* s, const void* g) {
    unsigned sa = (unsigned)__cvta_generic_to_shared(s);
    asm volatile("cp.async.ca.shared.global [%0], [%1], 16;\n" :: "r"(sa), "l"(g));
}
__device__ __forceinline__ void cpcommit() { asm volatile("cp.async.commit_group;\n"); }
__device__ __forceinline__ void cpwait()   { asm volatile("cp.async.wait_group 0;\n"); }

__device__ __forceinline__ void mma16816(float* c, const uint32_t* a, uint32_t b0, uint32_t b1) {
    asm volatile(
        "mma.sync.aligned.m16n8k16.row.col.f32.f16.f16.f32 "
        "{%0,%1,%2,%3}, {%4,%5,%6,%7}, {%8,%9}, {%0,%1,%2,%3};"
        : "+f"(c[0]), "+f"(c[1]), "+f"(c[2]), "+f"(c[3])
        : "r"(a[0]), "r"(a[1]), "r"(a[2]), "r"(a[3]), "r"(b0), "r"(b1));
}

// accurate-enough fast tanh: 1 - 2/(e^{2x}+1); handles +-inf saturation correctly
__device__ __forceinline__ float fast_tanh(float x) {
    float ex = __expf(2.0f * x);
    return 1.0f - __fdividef(2.0f, ex + 1.0f);
}

// ---------------- weight conversion kernels (fp32 -> fp16, run every launch) ----------------
__global__ void conv_w1k(const float* __restrict__ W1) {
    int i = blockIdx.x * blockDim.x + threadIdx.x;      // over E*H*IN_PAD = 524288
    if (i >= E_ * H_ * IN_PAD) return;
    int eh = i >> 7;           // / IN_PAD
    int k  = i & (IN_PAD - 1);
    g_w1[i] = __float2half(k < IN_RAW ? W1[eh * IN_RAW + k] : 0.0f);
}
__global__ void conv_w2k(const float* __restrict__ W) {
    int i = blockIdx.x * blockDim.x + threadIdx.x;      // 2097152
    g_w2[i] = __float2half(W[i]);
}
__global__ void conv_w3k(const float* __restrict__ W) {
    int i = blockIdx.x * blockDim.x + threadIdx.x;
    g_w3[i] = __float2half(W[i]);
}
__global__ void conv_w4k(const float* __restrict__ W) {
    int i = blockIdx.x * blockDim.x + threadIdx.x;      // 262144
    g_w4[i] = __float2half(W[i]);
}

// ---------------- one GEMM layer: out[BM x Ntot] = act(hin[BM x Ktot] @ W^T + bias) ----------------
// W is [Ntot][Ktot] (N rows, K contiguous) fp16 in global. Warp w owns columns
// [w*BN/8, (w+1)*BN/8) of each BN-wide N pass; all warps cover all 64 M rows.
template<int BN, bool LAST>
__device__ __forceinline__ void layer(const __half* __restrict__ hin,
                                      __half* __restrict__ hout,
                                      const __half* __restrict__ Wg, int Ktot,
                                      const float* __restrict__ bias,
                                      float* __restrict__ dynout,
                                      __half* __restrict__ wsh, int tid)
{
    const int warp = tid >> 5, lane = tid & 31;
    constexpr int WN  = BN / 8;            // per-warp n width
    constexpr int NTn = WN / 8;            // 16x8 n-tiles per warp
    constexpr int CH  = BN * WSTR;         // halves per weight chunk buffer
    constexpr int NLD = (BN * 64) / (8 * THREADS);  // cp16 per thread per chunk
    const int Ntot = LAST ? D_ : H_;

    for (int n0 = 0; n0 < Ntot; n0 += BN) {
        float acc[4][NTn][4];
        #pragma unroll
        for (int mt = 0; mt < 4; mt++)
            #pragma unroll
            for (int nt = 0; nt < NTn; nt++)
                #pragma unroll
                for (int i = 0; i < 4; i++) acc[mt][nt][i] = 0.0f;

        const int nch = Ktot / 64;

        // preload chunk 0 into buffer 0
        #pragma unroll
        for (int i = 0; i < NLD; i++) {
            int idx = i * THREADS + tid;
            int n = idx >> 3, k8 = (idx & 7) * 8;
            cp16(wsh + n * WSTR + k8, Wg + (size_t)(n0 + n) * Ktot + k8);
        }
        cpcommit();

        for (int kc = 0; kc < nch; kc++) {
            cpwait();
            __syncthreads();
            if (kc + 1 < nch) {
                __half* dstb = wsh + ((kc + 1) & 1) * CH;
                #pragma unroll
                for (int i = 0; i < NLD; i++) {
                    int idx = i * THREADS + tid;
                    int n = idx >> 3, k8 = (idx & 7) * 8;
                    cp16(dstb + n * WSTR + k8,
                         Wg + (size_t)(n0 + n) * Ktot + (kc + 1) * 64 + k8);
                }
                cpcommit();
            }
            const __half* wb = wsh + (kc & 1) * CH;

            #pragma unroll
            for (int ks = 0; ks < 4; ks++) {
                const int kk = kc * 64 + ks * 16;
                // A fragments (shared across all n-tiles of this warp)
                uint32_t a[4][4];
                const int arow = lane >> 2, acol = (lane & 3) * 2;
                #pragma unroll
                for (int mt = 0; mt < 4; mt++) {
                    const __half* p = hin + (mt * 16 + arow) * HSTR + kk + acol;
                    a[mt][0] = *(const uint32_t*)p;
                    a[mt][1] = *(const uint32_t*)(p + 8 * HSTR);
                    a[mt][2] = *(const uint32_t*)(p + 8);
                    a[mt][3] = *(const uint32_t*)(p + 8 * HSTR + 8);
                }
                #pragma unroll
                for (int nt = 0; nt < NTn; nt++) {
                    const int nloc = warp * WN + nt * 8 + (lane >> 2);
                    const __half* q = wb + nloc * WSTR + ks * 16 + (lane & 3) * 2;
                    uint32_t b0 = *(const uint32_t*)q;
                    uint32_t b1 = *(const uint32_t*)(q + 8);
                    #pragma unroll
                    for (int mt = 0; mt < 4; mt++) mma16816(acc[mt][nt], a[mt], b0, b1);
                }
            }
            // next iteration's cpwait+__syncthreads provides the needed barrier
        }

        // epilogue
        const float* bp = bias + n0;
        #pragma unroll
        for (int mt = 0; mt < 4; mt++) {
            #pragma unroll
            for (int nt = 0; nt < NTn; nt++) {
                const int cb = warp * WN + nt * 8 + (lane & 3) * 2;  // local col (even)
                const float2 bb = *(const float2*)(bp + cb);
                const int r0 = mt * 16 + (lane >> 2);
                float v0 = acc[mt][nt][0] + bb.x;
                float v1 = acc[mt][nt][1] + bb.y;
                float v2 = acc[mt][nt][2] + bb.x;
                float v3 = acc[mt][nt][3] + bb.y;
                if (!LAST) {
                    v0 = fast_tanh(v0); v1 = fast_tanh(v1);
                    v2 = fast_tanh(v2); v3 = fast_tanh(v3);
                    *(__half2*)(hout + r0 * HSTR + n0 + cb)       = __floats2half2_rn(v0, v1);
                    *(__half2*)(hout + (r0 + 8) * HSTR + n0 + cb) = __floats2half2_rn(v2, v3);
                } else {
                    float2 f01; f01.x = v0; f01.y = v1;
                    float2 f23; f23.x = v2; f23.y = v3;
                    *(float2*)(dynout + r0 * D_ + n0 + cb)       = f01;
                    *(float2*)(dynout + (r0 + 8) * D_ + n0 + cb) = f23;
                }
            }
        }
    }
}

// ---------------- fused per-tile, per-expert MLP kernel ----------------
__global__ __launch_bounds__(THREADS, 1)
void mlp_kernel(const float* __restrict__ x, const float* __restrict__ t,
                const float* __restrict__ omega,
                const float* __restrict__ b1, const float* __restrict__ b2,
                const float* __restrict__ b3, const float* __restrict__ b4)
{
    extern __shared__ __half sm[];
    __half* hb0 = sm;
    __half* hb1 = sm + BM * HSTR;
    __half* wsh = sm + 2 * BM * HSTR;

    const int e    = blockIdx.y;
    const int row0 = blockIdx.x * BM;
    const int tid  = threadIdx.x;

    // Build layer-1 input tile: [x(64) | t | sin(w t) | cos(w t) | zeros -> 128]
    const float tv = t[0];
    const float om = omega[e];
    const float sw = sinf(om * tv), cw = cosf(om * tv);
    for (int idx = tid; idx < BM * IN_PAD; idx += THREADS) {
        int r = idx >> 7, c = idx & (IN_PAD - 1);
        float v;
        if (c < 64)       v = x[(size_t)(row0 + r) * 64 + c];
        else if (c == 64) v = tv;
        else if (c == 65) v = sw;
        else if (c == 66) v = cw;
        else              v = 0.0f;
        hb0[r * HSTR + c] = __float2half(v);
    }
    // (layer()'s first cpwait+__syncthreads orders these writes vs. all reads)

    layer<256, false>(hb0, hb1, g_w1 + (size_t)e * H_ * IN_PAD, IN_PAD, b1 + e * H_, nullptr, wsh, tid);
    layer<256, false>(hb1, hb0, g_w2 + (size_t)e * H_ * H_,     H_,     b2 + e * H_, nullptr, wsh, tid);
    layer<256, false>(hb0, hb1, g_w3 + (size_t)e * H_ * H_,     H_,     b3 + e * H_, nullptr, wsh, tid);
    layer<64,  true >(hb1, nullptr, g_w4 + (size_t)e * D_ * H_, H_,     b4 + e * D_,
                      g_dyn + ((size_t)e * B_ + row0) * D_, wsh, tid);
}

// ---------------- expert-weighted combine (deterministic, no atomics) ----------------
__global__ void combine_k(const float* __restrict__ ew, float* __restrict__ out)
{
    int i = blockIdx.x * blockDim.x + threadIdx.x;   // over B*D
    int b = i >> 6;
    float s = 0.0f;
    #pragma unroll
    for (int e = 0; e < E_; e++)
        s += ew[b * E_ + e] * g_dyn[(size_t)e * B_ * D_ + i];
    out[i] = s;
}

// ---------------- launch ----------------
extern "C" void kernel_launch(void* const* d_in, const int* in_sizes, int n_in,
                              void* d_out, int out_size)
{
    const float* t  = (const float*)d_in[0];
    const float* x  = (const float*)d_in[1];
    const float* ew = (const float*)d_in[2];
    const float* om = (const float*)d_in[3];
    const float* W1 = (const float*)d_in[4];
    const float* b1 = (const float*)d_in[5];
    const float* W2 = (const float*)d_in[6];
    const float* b2 = (const float*)d_in[7];
    const float* W3 = (const float*)d_in[8];
    const float* b3 = (const float*)d_in[9];
    const float* W4 = (const float*)d_in[10];
    const float* b4 = (const float*)d_in[11];
    float* out = (float*)d_out;

    cudaFuncSetAttribute(mlp_kernel, cudaFuncAttributeMaxDynamicSharedMemorySize, SMEM_BYTES);

    conv_w1k<<<(E_ * H_ * IN_PAD) / 256, 256>>>(W1);
    conv_w2k<<<(E_ * H_ * H_) / 256, 256>>>(W2);
    conv_w3k<<<(E_ * H_ * H_) / 256, 256>>>(W3);
    conv_w4k<<<(E_ * D_ * H_) / 256, 256>>>(W4);

    dim3 grid(B_ / BM, E_);
    mlp_kernel<<<grid, THREADS, SMEM_BYTES>>>(x, t, om, b1, b2, b3, b4);

    combine_k<<<(B_ * D_) / 256, 256>>>(ew, out);
}

// round 4
// speedup vs baseline: 1.0639x; 1.0639x over previous
#include <cuda_runtime.h>
#include <cuda_fp16.h>
#include <cstdint>

// ---------------- problem constants ----------------
#define E_      8
#define D_      64
#define H_      512
#define B_      32768
#define IN_RAW  67
#define IN_PAD  128
#define BM      64            // batch rows per CTA
#define HSTR    520           // h-tile row stride (halves) -> 16B-chunk stride 65 (odd): LDSM/STS conflict-free
#define WSTR    72            // weight row stride (halves) -> conflict-free B LDS
#define THREADS 512
#define SMEM_BYTES ((2*BM*HSTR + 2*256*WSTR) * 2)   // 206,848 B

// ---------------- device scratch (allocation-free rule) ----------------
__device__ float  g_dyn[(size_t)E_ * B_ * D_];
__device__ __half g_w1[E_ * H_ * IN_PAD];
__device__ __half g_w2[(size_t)E_ * H_ * H_];
__device__ __half g_w3[(size_t)E_ * H_ * H_];
__device__ __half g_w4[E_ * D_ * H_];

// ---------------- helpers ----------------
__device__ __forceinline__ uint32_t smem_u32(const void* p) {
    uint32_t a;
    asm("{ .reg .u64 t; cvta.to.shared.u64 t, %1; cvt.u32.u64 %0, t; }" : "=r"(a) : "l"(p));
    return a;
}
__device__ __forceinline__ void cp16(const void* s, const void* g) {
    asm volatile("cp.async.cg.shared.global [%0], [%1], 16;\n" :: "r"(smem_u32(s)), "l"(g));
}
__device__ __forceinline__ void cpcommit() { asm volatile("cp.async.commit_group;\n"); }
template<int N> __device__ __forceinline__ void cpwait() {
    asm volatile("cp.async.wait_group %0;\n" :: "n"(N));
}
// ldmatrix x4: 16x16 half tile -> 4 regs matching mma.m16n8k16 A fragment
__device__ __forceinline__ void ldsm4(uint32_t* r, const void* p) {
    asm volatile("ldmatrix.sync.aligned.m8n8.x4.shared.b16 {%0,%1,%2,%3}, [%4];"
        : "=r"(r[0]), "=r"(r[1]), "=r"(r[2]), "=r"(r[3]) : "r"(smem_u32(p)));
}
__device__ __forceinline__ void mma16816(float* c, const uint32_t* a, uint32_t b0, uint32_t b1) {
    asm volatile(
        "mma.sync.aligned.m16n8k16.row.col.f32.f16.f16.f32 "
        "{%0,%1,%2,%3}, {%4,%5,%6,%7}, {%8,%9}, {%0,%1,%2,%3};"
        : "+f"(c[0]), "+f"(c[1]), "+f"(c[2]), "+f"(c[3])
        : "r"(a[0]), "r"(a[1]), "r"(a[2]), "r"(a[3]), "r"(b0), "r"(b1));
}
// accurate fast tanh: 1 - 2/(e^{2x}+1)
__device__ __forceinline__ float fast_tanh(float x) {
    float ex = __expf(2.0f * x);
    return 1.0f - __fdividef(2.0f, ex + 1.0f);
}

// ---------------- fp32 -> fp16 weight conversion ----------------
__global__ void conv_w1k(const float* __restrict__ W1) {
    int i = blockIdx.x * blockDim.x + threadIdx.x;
    int eh = i >> 7, k = i & (IN_PAD - 1);
    g_w1[i] = __float2half(k < IN_RAW ? W1[eh * IN_RAW + k] : 0.0f);
}
__global__ void conv_w2k(const float* __restrict__ W) {
    int i = blockIdx.x * blockDim.x + threadIdx.x; g_w2[i] = __float2half(W[i]);
}
__global__ void conv_w3k(const float* __restrict__ W) {
    int i = blockIdx.x * blockDim.x + threadIdx.x; g_w3[i] = __float2half(W[i]);
}
__global__ void conv_w4k(const float* __restrict__ W) {
    int i = blockIdx.x * blockDim.x + threadIdx.x; g_w4[i] = __float2half(W[i]);
}

// ---------------- one layer: hout[BM x Ntot] = act(hin[BM x Ktot] @ W^T + b) ----------------
// 16 warps: 2 m-groups (32 rows) x 8 n-groups (BN/8 cols each).
template<int BN, bool LAST>
__device__ __forceinline__ void layer(const __half* __restrict__ hin,
                                      __half* __restrict__ hout,
                                      const __half* __restrict__ Wg, int Ktot,
                                      const float* __restrict__ bias,
                                      float* __restrict__ dynout,
                                      __half* __restrict__ wsh, int tid)
{
    const int warp = tid >> 5, lane = tid & 31;
    const int mg = warp >> 3, ng = warp & 7;
    constexpr int WN  = BN / 8;            // per-warp n width
    constexpr int NTn = WN / 8;            // 16x8 n-tiles per warp
    constexpr int CH  = BN * WSTR;         // halves per weight buffer
    constexpr int NLD = (BN * 8) / THREADS;  // cp16 ops per thread per chunk
    const int Ntot = LAST ? D_ : H_;

    for (int n0 = 0; n0 < Ntot; n0 += BN) {
        float acc[2][NTn][4];
        #pragma unroll
        for (int mt = 0; mt < 2; mt++)
            #pragma unroll
            for (int nt = 0; nt < NTn; nt++)
                #pragma unroll
                for (int i = 0; i < 4; i++) acc[mt][nt][i] = 0.0f;

        const int nch = Ktot / 64;

        // preload chunk 0 -> buffer 0
        #pragma unroll
        for (int it = 0; it < NLD; it++) {
            int idx = it * THREADS + tid;
            int n = idx >> 3, k16 = idx & 7;
            cp16(wsh + n * WSTR + k16 * 8, Wg + (size_t)(n0 + n) * Ktot + k16 * 8);
        }
        cpcommit();

        #pragma unroll 1
        for (int kc = 0; kc < nch; kc++) {
            const int b = kc & 1;
            if (kc + 1 < nch) {
                __syncthreads();               // all warps done with math(kc-1): buf b^1 free
                __half* dstb = wsh + (b ^ 1) * CH;
                #pragma unroll
                for (int it = 0; it < NLD; it++) {
                    int idx = it * THREADS + tid;
                    int n = idx >> 3, k16 = idx & 7;
                    cp16(dstb + n * WSTR + k16 * 8,
                         Wg + (size_t)(n0 + n) * Ktot + (kc + 1) * 64 + k16 * 8);
                }
                cpcommit();
                cpwait<1>();                   // chunk kc arrived (kc+1 still in flight)
            } else {
                cpwait<0>();
            }
            __syncthreads();                   // publish chunk kc to all warps
            const __half* wb = wsh + b * CH;

            #pragma unroll
            for (int ks = 0; ks < 4; ks++) {
                const int kk = kc * 64 + ks * 16;
                uint32_t a[2][4];
                #pragma unroll
                for (int mt = 0; mt < 2; mt++)
                    ldsm4(a[mt], hin + (mg * 32 + mt * 16 + (lane & 15)) * HSTR
                                     + kk + ((lane >> 4) << 3));
                #pragma unroll
                for (int nt = 0; nt < NTn; nt++) {
                    const int nloc = ng * WN + nt * 8 + (lane >> 2);
                    const __half* q = wb + nloc * WSTR + ks * 16 + (lane & 3) * 2;
                    uint32_t b0 = *(const uint32_t*)q;
                    uint32_t b1 = *(const uint32_t*)(q + 8);
                    mma16816(acc[0][nt], a[0], b0, b1);
                    mma16816(acc[1][nt], a[1], b0, b1);
                }
            }
        }

        // epilogue
        const float* bp = bias + n0;
        #pragma unroll
        for (int mt = 0; mt < 2; mt++) {
            #pragma unroll
            for (int nt = 0; nt < NTn; nt++) {
                const int cb = ng * WN + nt * 8 + (lane & 3) * 2;
                const float2 bb = *(const float2*)(bp + cb);
                const int r0 = mg * 32 + mt * 16 + (lane >> 2);
                float v0 = acc[mt][nt][0] + bb.x;
                float v1 = acc[mt][nt][1] + bb.y;
                float v2 = acc[mt][nt][2] + bb.x;
                float v3 = acc[mt][nt][3] + bb.y;
                if (!LAST) {
                    v0 = fast_tanh(v0); v1 = fast_tanh(v1);
                    v2 = fast_tanh(v2); v3 = fast_tanh(v3);
                    *(__half2*)(hout + r0 * HSTR + n0 + cb)       = __floats2half2_rn(v0, v1);
                    *(__half2*)(hout + (r0 + 8) * HSTR + n0 + cb) = __floats2half2_rn(v2, v3);
                } else {
                    float2 f01; f01.x = v0; f01.y = v1;
                    float2 f23; f23.x = v2; f23.y = v3;
                    *(float2*)(dynout + r0 * D_ + n0 + cb)       = f01;
                    *(float2*)(dynout + (r0 + 8) * D_ + n0 + cb) = f23;
                }
            }
        }
    }
}

// ---------------- fused per-tile, per-expert MLP kernel ----------------
__global__ __launch_bounds__(THREADS, 1)
void mlp_kernel(const float* __restrict__ x, const float* __restrict__ t,
                const float* __restrict__ omega,
                const float* __restrict__ b1, const float* __restrict__ b2,
                const float* __restrict__ b3, const float* __restrict__ b4)
{
    extern __shared__ __half sm[];
    __half* hb0 = sm;
    __half* hb1 = sm + BM * HSTR;
    __half* wsh = sm + 2 * BM * HSTR;

    const int e    = blockIdx.y;
    const int row0 = blockIdx.x * BM;
    const int tid  = threadIdx.x;

    // Build layer-1 input tile: [x(64) | t | sin(wt) | cos(wt) | zeros -> 128]
    const float tv = t[0];
    const float om = omega[e];
    const float sw = sinf(om * tv), cw = cosf(om * tv);
    for (int idx = tid; idx < BM * IN_PAD; idx += THREADS) {
        int r = idx >> 7, c = idx & (IN_PAD - 1);
        float v;
        if (c < 64)       v = x[(size_t)(row0 + r) * 64 + c];
        else if (c == 64) v = tv;
        else if (c == 65) v = sw;
        else if (c == 66) v = cw;
        else              v = 0.0f;
        hb0[r * HSTR + c] = __float2half(v);
    }
    // (layer()'s first barriers order these writes before any LDSM reads)

    layer<256, false>(hb0, hb1, g_w1 + (size_t)e * H_ * IN_PAD, IN_PAD, b1 + e * H_, nullptr, wsh, tid);
    layer<256, false>(hb1, hb0, g_w2 + (size_t)e * H_ * H_,     H_,     b2 + e * H_, nullptr, wsh, tid);
    layer<256, false>(hb0, hb1, g_w3 + (size_t)e * H_ * H_,     H_,     b3 + e * H_, nullptr, wsh, tid);
    layer<64,  true >(hb1, nullptr, g_w4 + (size_t)e * D_ * H_, H_,     b4 + e * D_,
                      g_dyn + ((size_t)e * B_ + row0) * D_, wsh, tid);
}

// ---------------- expert-weighted combine (deterministic) ----------------
__global__ void combine_k(const float* __restrict__ ew, float* __restrict__ out)
{
    int i = blockIdx.x * blockDim.x + threadIdx.x;
    int b = i >> 6;
    float s = 0.0f;
    #pragma unroll
    for (int e = 0; e < E_; e++)
        s += ew[b * E_ + e] * g_dyn[(size_t)e * B_ * D_ + i];
    out[i] = s;
}

// ---------------- launch ----------------
extern "C" void kernel_launch(void* const* d_in, const int* in_sizes, int n_in,
                              void* d_out, int out_size)
{
    const float* t  = (const float*)d_in[0];
    const float* x  = (const float*)d_in[1];
    const float* ew = (const float*)d_in[2];
    const float* om = (const float*)d_in[3];
    const float* W1 = (const float*)d_in[4];
    const float* b1 = (const float*)d_in[5];
    const float* W2 = (const float*)d_in[6];
    const float* b2 = (const float*)d_in[7];
    const float* W3 = (const float*)d_in[8];
    const float* b3 = (const float*)d_in[9];
    const float* W4 = (const float*)d_in[10];
    const float* b4 = (const float*)d_in[11];
    float* out = (float*)d_out;

    cudaFuncSetAttribute(mlp_kernel, cudaFuncAttributeMaxDynamicSharedMemorySize, SMEM_BYTES);

    conv_w1k<<<(E_ * H_ * IN_PAD) / 256, 256>>>(W1);
    conv_w2k<<<(E_ * H_ * H_) / 256, 256>>>(W2);
    conv_w3k<<<(E_ * H_ * H_) / 256, 256>>>(W3);
    conv_w4k<<<(E_ * D_ * H_) / 256, 256>>>(W4);

    dim3 grid(B_ / BM, E_);
    mlp_kernel<<<grid, THREADS, SMEM_BYTES>>>(x, t, om, b1, b2, b3, b4);

    combine_k<<<(B_ * D_) / 256, 256>>>(ew, out);
}

// round 5
// speedup vs baseline: 1.4166x; 1.3316x over previous
#include <cuda_runtime.h>
#include <cuda_fp16.h>
#include <cstdint>

// ---------------- problem constants ----------------
#define E_      8
#define D_      64
#define H_      512
#define B_      32768
#define IN_RAW  67
#define BM      64            // batch rows per CTA
#define HSTR    520           // h-tile row stride (halves): LDSM/STS conflict-free
#define THREADS 512

// SMEM layout (bytes)
#define SM_BBUF   0           // 2 x 32KB weight chunk buffers
#define BSLOT     32768
#define SM_H0     65536       // h buffers: 64*520*2 = 66560 each
#define SM_H1     (SM_H0 + 66560)
#define SM_MBAR   (SM_H1 + 66560)    // 198656: full[2], empty[2] mbarriers
#define SM_TOTAL  (SM_MBAR + 64)

// ---------------- device scratch (allocation-free rule) ----------------
__device__ float g_dyn[(size_t)E_ * B_ * D_];
// re-tiled, SW128-swizzled fp16 weights (contiguous 32KB/8KB chunks)
__device__ __align__(128) char g_w1s[E_ * 4 * 32768];            // 1 MB : 2 passes x 2 chunks
__device__ __align__(128) char g_w2s[(size_t)E_ * 16 * 32768];   // 4 MB : 2 passes x 8 chunks
__device__ __align__(128) char g_w3s[(size_t)E_ * 16 * 32768];   // 4 MB
__device__ __align__(128) char g_w4s[E_ * 8 * 8192];             // 0.5 MB : 1 pass x 8 chunks (64-row)

// ---------------- low-level helpers ----------------
__device__ __forceinline__ uint32_t smem_u32(const void* p) {
    uint32_t a;
    asm("{ .reg .u64 t; cvta.to.shared.u64 t, %1; cvt.u32.u64 %0, t; }" : "=r"(a) : "l"(p));
    return a;
}
__device__ __forceinline__ void ldsm4(uint32_t* r, const void* p) {
    asm volatile("ldmatrix.sync.aligned.m8n8.x4.shared.b16 {%0,%1,%2,%3}, [%4];"
        : "=r"(r[0]), "=r"(r[1]), "=r"(r[2]), "=r"(r[3]) : "r"(smem_u32(p)));
}
__device__ __forceinline__ void ldsm2(uint32_t& r0, uint32_t& r1, const void* p) {
    asm volatile("ldmatrix.sync.aligned.m8n8.x2.shared.b16 {%0,%1}, [%2];"
        : "=r"(r0), "=r"(r1) : "r"(smem_u32(p)));
}
__device__ __forceinline__ void mma16816(float* c, const uint32_t* a, uint32_t b0, uint32_t b1) {
    asm volatile(
        "mma.sync.aligned.m16n8k16.row.col.f32.f16.f16.f32 "
        "{%0,%1,%2,%3}, {%4,%5,%6,%7}, {%8,%9}, {%0,%1,%2,%3};"
        : "+f"(c[0]), "+f"(c[1]), "+f"(c[2]), "+f"(c[3])
        : "r"(a[0]), "r"(a[1]), "r"(a[2]), "r"(a[3]), "r"(b0), "r"(b1));
}
__device__ __forceinline__ void mbar_init(uint32_t a, uint32_t c) {
    asm volatile("mbarrier.init.shared.b64 [%0], %1;" :: "r"(a), "r"(c) : "memory");
}
__device__ __forceinline__ void mbar_arrive(uint32_t a) {
    asm volatile("mbarrier.arrive.shared.b64 _, [%0];" :: "r"(a) : "memory");
}
__device__ __forceinline__ void mbar_expect_tx(uint32_t a, uint32_t bytes) {
    asm volatile("mbarrier.arrive.expect_tx.shared.b64 _, [%0], %1;" :: "r"(a), "r"(bytes) : "memory");
}
__device__ __forceinline__ void bulk_g2s(uint32_t sdst, const void* gsrc, uint32_t bytes, uint32_t mbar) {
    asm volatile(
        "cp.async.bulk.shared::cluster.global.mbarrier::complete_tx::bytes [%0], [%1], %2, [%3];"
        :: "r"(sdst), "l"(gsrc), "r"(bytes), "r"(mbar) : "memory");
}
__device__ __forceinline__ void mbar_wait(uint32_t mbar, uint32_t parity) {
    uint32_t done;
    asm volatile(
        "{ .reg .pred p; mbarrier.try_wait.parity.acquire.cta.shared::cta.b64 p, [%1], %2; selp.b32 %0, 1, 0, p; }"
        : "=r"(done) : "r"(mbar), "r"(parity) : "memory");
    if (!done) {
        asm volatile(
            "{ .reg .pred P1;\n"
            "W_%=:\n\t"
            "mbarrier.try_wait.parity.acquire.cta.shared::cta.b64 P1, [%0], %1, 0x989680;\n\t"
            "@P1 bra.uni D_%=;\n\t"
            "bra.uni W_%=;\n"
            "D_%=: }"
            :: "r"(mbar), "r"(parity) : "memory");
    }
}
// accurate fast tanh: 1 - 2/(e^{2x}+1)
__device__ __forceinline__ float fast_tanh(float x) {
    float ex = __expf(2.0f * x);
    return 1.0f - __fdividef(2.0f, ex + 1.0f);
}

// ---------------- weight re-tiling kernels (fp32 -> fp16, swizzled chunks) ----------------
// Chunk layout: NR rows x 64 k halves; byte (n*128 + 2k) stored at n*128 + ((2k) ^ ((n&7)<<4)).
__global__ void conv_w1s(const float* __restrict__ W1) {
    int i = blockIdx.x * blockDim.x + threadIdx.x;     // E*512*64 k-pairs (K padded to 128)
    int e = i >> 15, r = i & 32767;
    int n = r >> 6, kp = r & 63, k = kp * 2;
    int p = n >> 8, nl = n & 255, kc = k >> 6, kl = k & 63;
    size_t chunk = ((size_t)(e * 2 + p) * 2 + kc) * 32768;
    uint32_t off = (uint32_t)(nl * 128) + (((uint32_t)(kl * 2)) ^ ((uint32_t)(nl & 7) << 4));
    const float* s = W1 + ((size_t)e * 512 + n) * IN_RAW;
    float v0 = (k < IN_RAW) ? s[k] : 0.0f;
    float v1 = (k + 1 < IN_RAW) ? s[k + 1] : 0.0f;
    *(__half2*)(g_w1s + chunk + off) = __floats2half2_rn(v0, v1);
}
__global__ void conv_w23s(const float* __restrict__ W, char* __restrict__ dst) {
    int i = blockIdx.x * blockDim.x + threadIdx.x;     // E*512*256 k-pairs
    int e = i >> 17, r = i & 131071;
    int n = r >> 8, kp = r & 255, k = kp * 2;
    int p = n >> 8, nl = n & 255, kc = k >> 6, kl = k & 63;
    size_t chunk = ((size_t)(e * 2 + p) * 8 + kc) * 32768;
    uint32_t off = (uint32_t)(nl * 128) + (((uint32_t)(kl * 2)) ^ ((uint32_t)(nl & 7) << 4));
    const float* s = W + ((size_t)e * 512 + n) * 512 + k;
    *(__half2*)(dst + chunk + off) = __floats2half2_rn(s[0], s[1]);
}
__global__ void conv_w4s(const float* __restrict__ W4) {
    int i = blockIdx.x * blockDim.x + threadIdx.x;     // E*64*256 k-pairs
    int e = i >> 14, r = i & 16383;
    int n = r >> 8, kp = r & 255, k = kp * 2;
    int kc = k >> 6, kl = k & 63;
    size_t chunk = ((size_t)e * 8 + kc) * 8192;
    uint32_t off = (uint32_t)(n * 128) + (((uint32_t)(kl * 2)) ^ ((uint32_t)(n & 7) << 4));
    const float* s = W4 + ((size_t)e * 64 + n) * 512 + k;
    *(__half2*)(g_w4s + chunk + off) = __floats2half2_rn(s[0], s[1]);
}

// ---------------- mbarrier-ringed weight stream ----------------
struct Stream {
    uint32_t fullb[2], emptyb[2], bdst[2];
    int pc[2], cc[2];
    int gp, gc;
    bool leader;
};
__device__ __forceinline__ void produce(Stream& s, const void* src, uint32_t bytes) {
    int b = s.gp & 1;
    if (s.leader) {
        if (s.pc[b] > 0) mbar_wait(s.emptyb[b], (uint32_t)((s.pc[b] - 1) & 1));
        mbar_expect_tx(s.fullb[b], bytes);
        bulk_g2s(s.bdst[b], src, bytes, s.fullb[b]);
    }
    s.pc[b]++; s.gp++;
}
__device__ __forceinline__ int consume_wait(Stream& s) {
    int b = s.gc & 1;
    mbar_wait(s.fullb[b], (uint32_t)(s.cc[b] & 1));
    return b;
}
__device__ __forceinline__ void consume_done(Stream& s, bool wl) {
    int b = s.gc & 1;
    if (wl) mbar_arrive(s.emptyb[b]);
    s.cc[b]++; s.gc++;
}

// ---------------- per-chunk math ----------------
template<int NTn>
__device__ __forceinline__ void chunk_math(float (&acc)[2][NTn][4],
        const __half* __restrict__ hin, const char* __restrict__ wb,
        int kc, int mg, int ng, int lane)
{
    const int arow = mg * 32 + (lane & 15);
    const int acol = (lane >> 4) << 3;
    const int g = lane >> 3, lr = lane & 7;
    #pragma unroll
    for (int ks = 0; ks < 4; ks++) {
        const int kk = kc * 64 + ks * 16;
        uint32_t a[2][4];
        ldsm4(a[0], hin + arow * HSTR + kk + acol);
        ldsm4(a[1], hin + (arow + 16) * HSTR + kk + acol);
        if constexpr (NTn == 4) {
            #pragma unroll
            for (int ntp = 0; ntp < 2; ntp++) {
                const int nrow = ng * 32 + ntp * 16 + ((g >> 1) << 3) + lr;
                const uint32_t j = (uint32_t)(ks * 2 + (g & 1));
                const char* p = wb + nrow * 128 + ((j << 4) ^ ((uint32_t)(nrow & 7) << 4));
                uint32_t b[4];
                ldsm4(b, p);
                mma16816(acc[0][2 * ntp],     a[0], b[0], b[1]);
                mma16816(acc[1][2 * ntp],     a[1], b[0], b[1]);
                mma16816(acc[0][2 * ntp + 1], a[0], b[2], b[3]);
                mma16816(acc[1][2 * ntp + 1], a[1], b[2], b[3]);
            }
        } else {
            const int nrow = ng * 8 + lr;
            const uint32_t j = (uint32_t)(ks * 2 + (g & 1));
            const char* p = wb + nrow * 128 + ((j << 4) ^ ((uint32_t)(nrow & 7) << 4));
            uint32_t b0, b1;
            ldsm2(b0, b1, p);
            mma16816(acc[0][0], a[0], b0, b1);
            mma16816(acc[1][0], a[1], b0, b1);
        }
    }
}

// ---------------- one N-pass (NR cols), with cross-pass prefetch ----------------
template<int NR, bool LAST>
__device__ __forceinline__ void run_pass(Stream& S, char* smc,
        const __half* __restrict__ hin, __half* __restrict__ hout,
        float* __restrict__ dynout,
        const char* __restrict__ cur, int nch,
        const char* __restrict__ nxt, uint32_t nxt_bytes, int nxt_n,
        const float* __restrict__ bias, int n0,
        int warp, int lane)
{
    constexpr int WN = NR / 8, NTn = WN / 8;
    constexpr uint32_t BYTES = (uint32_t)NR * 128;
    const int mg = warp >> 3, ng = warp & 7;
    const bool wl = (lane == 0);

    float acc[2][NTn][4];
    #pragma unroll
    for (int mt = 0; mt < 2; mt++)
        #pragma unroll
        for (int nt = 0; nt < NTn; nt++)
            #pragma unroll
            for (int i = 0; i < 4; i++) acc[mt][nt][i] = 0.0f;

    #pragma unroll 1
    for (int kc = 0; kc < nch; kc++) {
        int b = consume_wait(S);
        chunk_math<NTn>(acc, hin, smc + b * BSLOT, kc, mg, ng, lane);
        consume_done(S, wl);
        int pidx = kc + 2;
        if (pidx < nch)               produce(S, cur + (size_t)pidx * BYTES, BYTES);
        else if (pidx - nch < nxt_n)  produce(S, nxt + (size_t)(pidx - nch) * nxt_bytes, nxt_bytes);
    }

    // epilogue
    #pragma unroll
    for (int mt = 0; mt < 2; mt++) {
        #pragma unroll
        for (int nt = 0; nt < NTn; nt++) {
            const int cb = ng * WN + nt * 8 + (lane & 3) * 2;
            const float2 bb = *(const float2*)(bias + cb);
            const int r0 = mg * 32 + mt * 16 + (lane >> 2);
            float v0 = acc[mt][nt][0] + bb.x;
            float v1 = acc[mt][nt][1] + bb.y;
            float v2 = acc[mt][nt][2] + bb.x;
            float v3 = acc[mt][nt][3] + bb.y;
            if (!LAST) {
                v0 = fast_tanh(v0); v1 = fast_tanh(v1);
                v2 = fast_tanh(v2); v3 = fast_tanh(v3);
                *(__half2*)(hout + r0 * HSTR + n0 + cb)       = __floats2half2_rn(v0, v1);
                *(__half2*)(hout + (r0 + 8) * HSTR + n0 + cb) = __floats2half2_rn(v2, v3);
            } else {
                float2 f01; f01.x = v0; f01.y = v1;
                float2 f23; f23.x = v2; f23.y = v3;
                *(float2*)(dynout + (size_t)r0 * D_ + cb)       = f01;
                *(float2*)(dynout + (size_t)(r0 + 8) * D_ + cb) = f23;
            }
        }
    }
}

// ---------------- fused per-tile, per-expert MLP kernel ----------------
__global__ __launch_bounds__(THREADS, 1)
void mlp_kernel(const float* __restrict__ x, const float* __restrict__ t,
                const float* __restrict__ omega,
                const float* __restrict__ b1, const float* __restrict__ b2,
                const float* __restrict__ b3, const float* __restrict__ b4)
{
    extern __shared__ __align__(1024) char smc[];
    __half* h0 = (__half*)(smc + SM_H0);
    __half* h1 = (__half*)(smc + SM_H1);
    const uint32_t mb = smem_u32(smc + SM_MBAR);

    const int tid  = threadIdx.x;
    const int warp = tid >> 5, lane = tid & 31;
    const int e    = blockIdx.y;
    const int row0 = blockIdx.x * BM;

    Stream S;
    S.fullb[0] = mb; S.fullb[1] = mb + 8;
    S.emptyb[0] = mb + 16; S.emptyb[1] = mb + 24;
    S.bdst[0] = smem_u32(smc); S.bdst[1] = smem_u32(smc + BSLOT);
    S.pc[0] = S.pc[1] = S.cc[0] = S.cc[1] = 0;
    S.gp = S.gc = 0;
    S.leader = (tid == 0);

    if (tid == 0) {
        mbar_init(S.fullb[0], 1);  mbar_init(S.fullb[1], 1);
        mbar_init(S.emptyb[0], 16); mbar_init(S.emptyb[1], 16);
        asm volatile("fence.proxy.async.shared::cta;" ::: "memory");
    }
    __syncthreads();

    // chunk bases
    const char* w1p0 = g_w1s + (size_t)(e * 2 + 0) * 2 * 32768;
    const char* w1p1 = g_w1s + (size_t)(e * 2 + 1) * 2 * 32768;
    const char* w2p0 = g_w2s + (size_t)(e * 2 + 0) * 8 * 32768;
    const char* w2p1 = g_w2s + (size_t)(e * 2 + 1) * 8 * 32768;
    const char* w3p0 = g_w3s + (size_t)(e * 2 + 0) * 8 * 32768;
    const char* w3p1 = g_w3s + (size_t)(e * 2 + 1) * 8 * 32768;
    const char* w4c  = g_w4s + (size_t)e * 8 * 8192;

    // prefetch L1 pass0 chunks
    produce(S, w1p0, 32768);
    produce(S, w1p0 + 32768, 32768);

    // build layer-1 A tile: [x(64) | t | sin(wt) | cos(wt) | zeros -> 128]
    const float tv = t[0];
    const float om = omega[e];
    const float sw = sinf(om * tv), cw = cosf(om * tv);
    for (int idx = tid; idx < BM * 128; idx += THREADS) {
        int r = idx >> 7, c = idx & 127;
        float v;
        if (c < 64)       v = x[(size_t)(row0 + r) * 64 + c];
        else if (c == 64) v = tv;
        else if (c == 65) v = sw;
        else if (c == 66) v = cw;
        else              v = 0.0f;
        h0[r * HSTR + c] = __float2half(v);
    }
    __syncthreads();

    float* dyn = g_dyn + ((size_t)e * B_ + row0) * D_;

    // Layer 1 (K=128 padded): two 256-col passes
    run_pass<256, false>(S, smc, h0, h1, nullptr, w1p0, 2, w1p1, 32768, 2, b1 + e * H_,       0, warp, lane);
    run_pass<256, false>(S, smc, h0, h1, nullptr, w1p1, 2, w2p0, 32768, 2, b1 + e * H_ + 256, 256, warp, lane);
    __syncthreads();
    // Layer 2
    run_pass<256, false>(S, smc, h1, h0, nullptr, w2p0, 8, w2p1, 32768, 2, b2 + e * H_,       0, warp, lane);
    run_pass<256, false>(S, smc, h1, h0, nullptr, w2p1, 8, w3p0, 32768, 2, b2 + e * H_ + 256, 256, warp, lane);
    __syncthreads();
    // Layer 3
    run_pass<256, false>(S, smc, h0, h1, nullptr, w3p0, 8, w3p1, 32768, 2, b3 + e * H_,       0, warp, lane);
    run_pass<256, false>(S, smc, h0, h1, nullptr, w3p1, 8, w4c,  8192,  2, b3 + e * H_ + 256, 256, warp, lane);
    __syncthreads();
    // Layer 4 (N=64, fp32 out)
    run_pass<64, true>(S, smc, h1, nullptr, dyn, w4c, 8, nullptr, 0, 0, b4 + e * D_, 0, warp, lane);
}

// ---------------- expert-weighted combine (deterministic) ----------------
__global__ void combine_k(const float* __restrict__ ew, float* __restrict__ out)
{
    int i = blockIdx.x * blockDim.x + threadIdx.x;
    int b = i >> 6;
    float s = 0.0f;
    #pragma unroll
    for (int e = 0; e < E_; e++)
        s += ew[b * E_ + e] * g_dyn[(size_t)e * B_ * D_ + i];
    out[i] = s;
}

// ---------------- launch ----------------
extern "C" void kernel_launch(void* const* d_in, const int* in_sizes, int n_in,
                              void* d_out, int out_size)
{
    const float* t  = (const float*)d_in[0];
    const float* x  = (const float*)d_in[1];
    const float* ew = (const float*)d_in[2];
    const float* om = (const float*)d_in[3];
    const float* W1 = (const float*)d_in[4];
    const float* b1 = (const float*)d_in[5];
    const float* W2 = (const float*)d_in[6];
    const float* b2 = (const float*)d_in[7];
    const float* W3 = (const float*)d_in[8];
    const float* b3 = (const float*)d_in[9];
    const float* W4 = (const float*)d_in[10];
    const float* b4 = (const float*)d_in[11];
    float* out = (float*)d_out;

    cudaFuncSetAttribute(mlp_kernel, cudaFuncAttributeMaxDynamicSharedMemorySize, SM_TOTAL);

    char* w2s_ptr = nullptr;
    char* w3s_ptr = nullptr;
    cudaGetSymbolAddress((void**)&w2s_ptr, g_w2s);
    cudaGetSymbolAddress((void**)&w3s_ptr, g_w3s);

    conv_w1s<<<(E_ * 512 * 64) / 256, 256>>>(W1);
    conv_w23s<<<(E_ * 512 * 256) / 256, 256>>>(W2, w2s_ptr);
    conv_w23s<<<(E_ * 512 * 256) / 256, 256>>>(W3, w3s_ptr);
    conv_w4s<<<(E_ * 64 * 256) / 256, 256>>>(W4);

    dim3 grid(B_ / BM, E_);
    mlp_kernel<<<grid, THREADS, SM_TOTAL>>>(x, t, om, b1, b2, b3, b4);

    combine_k<<<(B_ * D_) / 256, 256>>>(ew, out);
}

// round 6
// speedup vs baseline: 1.4641x; 1.0335x over previous
#include <cuda_runtime.h>
#include <cuda_fp16.h>
#include <cstdint>

// ---------------- problem constants ----------------
#define E_      8
#define D_      64
#define H_      512
#define B_      32768
#define IN_RAW  67
#define BM      64            // batch rows per CTA
#define HSTR    520           // h-tile row stride (halves): LDSM/STS conflict-free
#define THREADS 512

// SMEM layout (bytes)
#define BSLOT     32768
#define SM_H0     65536       // h buffers: 64*520*2 = 66560 each
#define SM_H1     (SM_H0 + 66560)
#define SM_MBAR   (SM_H1 + 66560)
#define SM_TOTAL  (SM_MBAR + 64)

// total weight chunks streamed per CTA
#define NCHUNKS 42

// ---------------- device scratch (allocation-free rule) ----------------
__device__ float g_dyn[(size_t)E_ * B_ * D_];
__device__ float g_b1eff[E_ * H_];
// re-tiled, SW128-swizzled fp16 weights (contiguous 32KB/8KB chunks)
__device__ __align__(128) char g_w1s[E_ * 2 * 32768];            // 0.5 MB : 2 passes x 1 chunk (K=64)
__device__ __align__(128) char g_w2s[(size_t)E_ * 16 * 32768];   // 4 MB : 2 passes x 8 chunks
__device__ __align__(128) char g_w3s[(size_t)E_ * 16 * 32768];   // 4 MB
__device__ __align__(128) char g_w4s[E_ * 8 * 8192];             // 0.5 MB : 8 chunks (64-row)

// ---------------- low-level helpers ----------------
__device__ __forceinline__ uint32_t smem_u32(const void* p) {
    uint32_t a;
    asm("{ .reg .u64 t; cvta.to.shared.u64 t, %1; cvt.u32.u64 %0, t; }" : "=r"(a) : "l"(p));
    return a;
}
__device__ __forceinline__ void ldsm4(uint32_t* r, const void* p) {
    asm volatile("ldmatrix.sync.aligned.m8n8.x4.shared.b16 {%0,%1,%2,%3}, [%4];"
        : "=r"(r[0]), "=r"(r[1]), "=r"(r[2]), "=r"(r[3]) : "r"(smem_u32(p)));
}
__device__ __forceinline__ void ldsm2(uint32_t& r0, uint32_t& r1, const void* p) {
    asm volatile("ldmatrix.sync.aligned.m8n8.x2.shared.b16 {%0,%1}, [%2];"
        : "=r"(r0), "=r"(r1) : "r"(smem_u32(p)));
}
__device__ __forceinline__ void mma16816(float* c, const uint32_t* a, uint32_t b0, uint32_t b1) {
    asm volatile(
        "mma.sync.aligned.m16n8k16.row.col.f32.f16.f16.f32 "
        "{%0,%1,%2,%3}, {%4,%5,%6,%7}, {%8,%9}, {%0,%1,%2,%3};"
        : "+f"(c[0]), "+f"(c[1]), "+f"(c[2]), "+f"(c[3])
        : "r"(a[0]), "r"(a[1]), "r"(a[2]), "r"(a[3]), "r"(b0), "r"(b1));
}
__device__ __forceinline__ void mbar_init(uint32_t a, uint32_t c) {
    asm volatile("mbarrier.init.shared.b64 [%0], %1;" :: "r"(a), "r"(c) : "memory");
}
__device__ __forceinline__ void mbar_arrive(uint32_t a) {
    asm volatile("mbarrier.arrive.shared.b64 _, [%0];" :: "r"(a) : "memory");
}
__device__ __forceinline__ void mbar_expect_tx(uint32_t a, uint32_t bytes) {
    asm volatile("mbarrier.arrive.expect_tx.shared.b64 _, [%0], %1;" :: "r"(a), "r"(bytes) : "memory");
}
__device__ __forceinline__ void bulk_g2s(uint32_t sdst, const void* gsrc, uint32_t bytes, uint32_t mbar) {
    asm volatile(
        "cp.async.bulk.shared::cluster.global.mbarrier::complete_tx::bytes [%0], [%1], %2, [%3];"
        :: "r"(sdst), "l"(gsrc), "r"(bytes), "r"(mbar) : "memory");
}
__device__ __forceinline__ void mbar_wait(uint32_t mbar, uint32_t parity) {
    uint32_t done;
    asm volatile(
        "{ .reg .pred p; mbarrier.try_wait.parity.acquire.cta.shared::cta.b64 p, [%1], %2; selp.b32 %0, 1, 0, p; }"
        : "=r"(done) : "r"(mbar), "r"(parity) : "memory");
    if (!done) {
        asm volatile(
            "{ .reg .pred P1;\n"
            "W_%=:\n\t"
            "mbarrier.try_wait.parity.acquire.cta.shared::cta.b64 P1, [%0], %1, 0x989680;\n\t"
            "@P1 bra.uni D_%=;\n\t"
            "bra.uni W_%=;\n"
            "D_%=: }"
            :: "r"(mbar), "r"(parity) : "memory");
    }
}
// accurate fast tanh: 1 - 2/(e^{2x}+1)
__device__ __forceinline__ float fast_tanh(float x) {
    float ex = __expf(2.0f * x);
    return 1.0f - __fdividef(2.0f, ex + 1.0f);
}

// ---------------- weight prep (fused small kernel: W1 retile + W4 retile + b1eff) ----------------
__global__ void conv_small(const float* __restrict__ W1, const float* __restrict__ W4,
                           const float* __restrict__ b1, const float* __restrict__ t,
                           const float* __restrict__ omega)
{
    int i = blockIdx.x * blockDim.x + threadIdx.x;
    if (i < 131072) {
        // W1[:, :64] retile: E*512 rows x 32 k-pairs
        int e = i >> 14, r = i & 16383;
        int n = r >> 5, k = (r & 31) * 2;
        int p = n >> 8, nl = n & 255;
        size_t chunk = (size_t)(e * 2 + p) * 32768;
        uint32_t off = (uint32_t)(nl * 128) + (((uint32_t)(k * 2)) ^ ((uint32_t)(nl & 7) << 4));
        const float* s = W1 + ((size_t)e * 512 + n) * IN_RAW + k;
        *(__half2*)(g_w1s + chunk + off) = __floats2half2_rn(s[0], s[1]);
    } else if (i < 262144) {
        // W4 retile: E*64 rows x 256 k-pairs
        int j = i - 131072;
        int e = j >> 14, r = j & 16383;
        int n = r >> 8, k = (r & 255) * 2;
        int kc = k >> 6, kl = k & 63;
        size_t chunk = ((size_t)e * 8 + kc) * 8192;
        uint32_t off = (uint32_t)(n * 128) + (((uint32_t)(kl * 2)) ^ ((uint32_t)(n & 7) << 4));
        const float* s = W4 + ((size_t)e * 64 + n) * 512 + k;
        *(__half2*)(g_w4s + chunk + off) = __floats2half2_rn(s[0], s[1]);
    } else if (i < 262144 + E_ * H_) {
        // effective layer-1 bias: b1 + t*W1[:,64] + sin*W1[:,65] + cos*W1[:,66] (fp32)
        int j = i - 262144;
        int e = j >> 9;
        float tv = t[0], om = omega[e];
        const float* w = W1 + (size_t)j * IN_RAW;
        g_b1eff[j] = b1[j] + tv * w[64] + sinf(om * tv) * w[65] + cosf(om * tv) * w[66];
    }
}
__global__ void conv_w23s(const float* __restrict__ W, char* __restrict__ dst) {
    int i = blockIdx.x * blockDim.x + threadIdx.x;     // E*512*256 k-pairs
    int e = i >> 17, r = i & 131071;
    int n = r >> 8, k = (r & 255) * 2;
    int p = n >> 8, nl = n & 255, kc = k >> 6, kl = k & 63;
    size_t chunk = ((size_t)(e * 2 + p) * 8 + kc) * 32768;
    uint32_t off = (uint32_t)(nl * 128) + (((uint32_t)(kl * 2)) ^ ((uint32_t)(nl & 7) << 4));
    const float* s = W + ((size_t)e * 512 + n) * 512 + k;
    *(__half2*)(dst + chunk + off) = __floats2half2_rn(s[0], s[1]);
}

// ---------------- global chunk schedule + mbarrier-ringed stream ----------------
struct Stream {
    uint32_t fullb[2], emptyb[2], bdst[2];
    int pc[2], cc[2];
    int gp, gc;
    bool leader;
    const char* w1b;    // per-expert bases
    const char* w2b;
    const char* w3b;
    const char* w4b;
};
__device__ __forceinline__ void produce_next(Stream& s) {
    int i = s.gp;
    if (i >= NCHUNKS) return;
    const char* p;
    uint32_t bytes;
    if (i < 2)       { p = s.w1b + (size_t)i * 32768;            bytes = 32768; }
    else if (i < 18) { p = s.w2b + (size_t)(i - 2) * 32768;      bytes = 32768; }
    else if (i < 34) { p = s.w3b + (size_t)(i - 18) * 32768;     bytes = 32768; }
    else             { p = s.w4b + (size_t)(i - 34) * 8192;      bytes = 8192;  }
    int b = i & 1;
    if (s.leader) {
        if (s.pc[b] > 0) mbar_wait(s.emptyb[b], (uint32_t)((s.pc[b] - 1) & 1));
        mbar_expect_tx(s.fullb[b], bytes);
        bulk_g2s(s.bdst[b], p, bytes, s.fullb[b]);
    }
    s.pc[b]++; s.gp++;
}
__device__ __forceinline__ int consume_wait(Stream& s) {
    int b = s.gc & 1;
    mbar_wait(s.fullb[b], (uint32_t)(s.cc[b] & 1));
    return b;
}
__device__ __forceinline__ void consume_done(Stream& s, bool wl) {
    int b = s.gc & 1;
    if (wl) mbar_arrive(s.emptyb[b]);
    s.cc[b]++; s.gc++;
}

// ---------------- per-chunk math ----------------
template<int NTn>
__device__ __forceinline__ void chunk_math(float (&acc)[2][NTn][4],
        const __half* __restrict__ hin, const char* __restrict__ wb,
        int kc, int mg, int ng, int lane)
{
    const int arow = mg * 32 + (lane & 15);
    const int acol = (lane >> 4) << 3;
    const int g = lane >> 3, lr = lane & 7;
    #pragma unroll
    for (int ks = 0; ks < 4; ks++) {
        const int kk = kc * 64 + ks * 16;
        uint32_t a[2][4];
        ldsm4(a[0], hin + arow * HSTR + kk + acol);
        ldsm4(a[1], hin + (arow + 16) * HSTR + kk + acol);
        if constexpr (NTn == 4) {
            #pragma unroll
            for (int ntp = 0; ntp < 2; ntp++) {
                const int nrow = ng * 32 + ntp * 16 + ((g >> 1) << 3) + lr;
                const uint32_t j = (uint32_t)(ks * 2 + (g & 1));
                const char* p = wb + nrow * 128 + ((j << 4) ^ ((uint32_t)(nrow & 7) << 4));
                uint32_t b[4];
                ldsm4(b, p);
                mma16816(acc[0][2 * ntp],     a[0], b[0], b[1]);
                mma16816(acc[1][2 * ntp],     a[1], b[0], b[1]);
                mma16816(acc[0][2 * ntp + 1], a[0], b[2], b[3]);
                mma16816(acc[1][2 * ntp + 1], a[1], b[2], b[3]);
            }
        } else {
            const int nrow = ng * 8 + lr;
            const uint32_t j = (uint32_t)(ks * 2 + (g & 1));
            const char* p = wb + nrow * 128 + ((j << 4) ^ ((uint32_t)(nrow & 7) << 4));
            uint32_t b0, b1;
            ldsm2(b0, b1, p);
            mma16816(acc[0][0], a[0], b0, b1);
            mma16816(acc[1][0], a[1], b0, b1);
        }
    }
}

// ---------------- one N-pass (NR cols) ----------------
template<int NR, bool LAST>
__device__ __forceinline__ void run_pass(Stream& S, char* smc,
        const __half* __restrict__ hin, __half* __restrict__ hout,
        float* __restrict__ dynout,
        int nch,
        const float* __restrict__ bias, int n0,
        int warp, int lane)
{
    constexpr int WN = NR / 8, NTn = WN / 8;
    const int mg = warp >> 3, ng = warp & 7;
    const bool wl = (lane == 0);

    float acc[2][NTn][4];
    #pragma unroll
    for (int mt = 0; mt < 2; mt++)
        #pragma unroll
        for (int nt = 0; nt < NTn; nt++)
            #pragma unroll
            for (int i = 0; i < 4; i++) acc[mt][nt][i] = 0.0f;

    #pragma unroll 1
    for (int kc = 0; kc < nch; kc++) {
        int b = consume_wait(S);
        chunk_math<NTn>(acc, hin, smc + b * BSLOT, kc, mg, ng, lane);
        consume_done(S, wl);
        produce_next(S);
    }

    // epilogue
    #pragma unroll
    for (int mt = 0; mt < 2; mt++) {
        #pragma unroll
        for (int nt = 0; nt < NTn; nt++) {
            const int cb = ng * WN + nt * 8 + (lane & 3) * 2;
            const float2 bb = *(const float2*)(bias + cb);
            const int r0 = mg * 32 + mt * 16 + (lane >> 2);
            float v0 = acc[mt][nt][0] + bb.x;
            float v1 = acc[mt][nt][1] + bb.y;
            float v2 = acc[mt][nt][2] + bb.x;
            float v3 = acc[mt][nt][3] + bb.y;
            if (!LAST) {
                v0 = fast_tanh(v0); v1 = fast_tanh(v1);
                v2 = fast_tanh(v2); v3 = fast_tanh(v3);
                *(__half2*)(hout + r0 * HSTR + n0 + cb)       = __floats2half2_rn(v0, v1);
                *(__half2*)(hout + (r0 + 8) * HSTR + n0 + cb) = __floats2half2_rn(v2, v3);
            } else {
                float2 f01; f01.x = v0; f01.y = v1;
                float2 f23; f23.x = v2; f23.y = v3;
                *(float2*)(dynout + (size_t)r0 * D_ + cb)       = f01;
                *(float2*)(dynout + (size_t)(r0 + 8) * D_ + cb) = f23;
            }
        }
    }
}

// ---------------- fused per-tile, per-expert MLP kernel ----------------
__global__ __launch_bounds__(THREADS, 1)
void mlp_kernel(const float* __restrict__ x,
                const float* __restrict__ b2, const float* __restrict__ b3,
                const float* __restrict__ b4)
{
    extern __shared__ __align__(1024) char smc[];
    __half* h0 = (__half*)(smc + SM_H0);
    __half* h1 = (__half*)(smc + SM_H1);
    const uint32_t mb = smem_u32(smc + SM_MBAR);

    const int tid  = threadIdx.x;
    const int warp = tid >> 5, lane = tid & 31;
    const int e    = blockIdx.y;
    const int row0 = blockIdx.x * BM;

    Stream S;
    S.fullb[0] = mb; S.fullb[1] = mb + 8;
    S.emptyb[0] = mb + 16; S.emptyb[1] = mb + 24;
    S.bdst[0] = smem_u32(smc); S.bdst[1] = smem_u32(smc + BSLOT);
    S.pc[0] = S.pc[1] = S.cc[0] = S.cc[1] = 0;
    S.gp = S.gc = 0;
    S.leader = (tid == 0);
    S.w1b = g_w1s + (size_t)e * 2 * 32768;
    S.w2b = g_w2s + (size_t)e * 16 * 32768;
    S.w3b = g_w3s + (size_t)e * 16 * 32768;
    S.w4b = g_w4s + (size_t)e * 8 * 8192;

    if (tid == 0) {
        mbar_init(S.fullb[0], 1);  mbar_init(S.fullb[1], 1);
        mbar_init(S.emptyb[0], 16); mbar_init(S.emptyb[1], 16);
        asm volatile("fence.proxy.async.shared::cta;" ::: "memory");
    }
    __syncthreads();

    // prefetch first two chunks
    produce_next(S);
    produce_next(S);

    // build layer-1 A tile: just x (64 cols, fp16)
    for (int idx = tid; idx < BM * 64; idx += THREADS) {
        int r = idx >> 6, c = idx & 63;
        h0[r * HSTR + c] = __float2half(x[(size_t)(row0 + r) * 64 + c]);
    }
    __syncthreads();

    float* dyn = g_dyn + ((size_t)e * B_ + row0) * D_;
    const float* b1e = g_b1eff + e * H_;

    // Layer 1 (K=64): two 256-col passes, trig folded into g_b1eff
    run_pass<256, false>(S, smc, h0, h1, nullptr, 1, b1e,             0,   warp, lane);
    run_pass<256, false>(S, smc, h0, h1, nullptr, 1, b1e + 256,       256, warp, lane);
    __syncthreads();
    // Layer 2
    run_pass<256, false>(S, smc, h1, h0, nullptr, 8, b2 + e * H_,       0,   warp, lane);
    run_pass<256, false>(S, smc, h1, h0, nullptr, 8, b2 + e * H_ + 256, 256, warp, lane);
    __syncthreads();
    // Layer 3
    run_pass<256, false>(S, smc, h0, h1, nullptr, 8, b3 + e * H_,       0,   warp, lane);
    run_pass<256, false>(S, smc, h0, h1, nullptr, 8, b3 + e * H_ + 256, 256, warp, lane);
    __syncthreads();
    // Layer 4 (N=64, fp32 out)
    run_pass<64, true>(S, smc, h1, nullptr, dyn, 8, b4 + e * D_, 0, warp, lane);
}

// ---------------- expert-weighted combine (deterministic) ----------------
__global__ void combine_k(const float* __restrict__ ew, float* __restrict__ out)
{
    int i = blockIdx.x * blockDim.x + threadIdx.x;
    int b = i >> 6;
    float s = 0.0f;
    #pragma unroll
    for (int e = 0; e < E_; e++)
        s += ew[b * E_ + e] * g_dyn[(size_t)e * B_ * D_ + i];
    out[i] = s;
}

// ---------------- launch ----------------
extern "C" void kernel_launch(void* const* d_in, const int* in_sizes, int n_in,
                              void* d_out, int out_size)
{
    const float* t  = (const float*)d_in[0];
    const float* x  = (const float*)d_in[1];
    const float* ew = (const float*)d_in[2];
    const float* om = (const float*)d_in[3];
    const float* W1 = (const float*)d_in[4];
    const float* b1 = (const float*)d_in[5];
    const float* W2 = (const float*)d_in[6];
    const float* b2 = (const float*)d_in[7];
    const float* W3 = (const float*)d_in[8];
    const float* b3 = (const float*)d_in[9];
    const float* W4 = (const float*)d_in[10];
    const float* b4 = (const float*)d_in[11];
    float* out = (float*)d_out;

    cudaFuncSetAttribute(mlp_kernel, cudaFuncAttributeMaxDynamicSharedMemorySize, SM_TOTAL);

    char* w2s_ptr = nullptr;
    char* w3s_ptr = nullptr;
    cudaGetSymbolAddress((void**)&w2s_ptr, g_w2s);
    cudaGetSymbolAddress((void**)&w3s_ptr, g_w3s);

    // launch order chosen so mlp_kernel is our 4th launch (ncu sampling lands on it)
    conv_small<<<(262144 + E_ * H_ + 255) / 256, 256>>>(W1, W4, b1, t, om);
    conv_w23s<<<(E_ * 512 * 256) / 256, 256>>>(W2, w2s_ptr);
    conv_w23s<<<(E_ * 512 * 256) / 256, 256>>>(W3, w3s_ptr);

    dim3 grid(B_ / BM, E_);
    mlp_kernel<<<grid, THREADS, SM_TOTAL>>>(x, b2, b3, b4);

    combine_k<<<(B_ * D_) / 256, 256>>>(ew, out);
}

// round 7
// speedup vs baseline: 1.6301x; 1.1134x over previous
#include <cuda_runtime.h>
#include <cuda_fp16.h>
#include <cstdint>

// ---------------- problem constants ----------------
#define E_      8
#define D_      64
#define H_      512
#define B_      32768
#define IN_RAW  67
#define BM      64            // batch rows per CTA
#define HSTR    520           // h-tile row stride (halves)
#define THREADS 512

// SMEM layout (bytes)
#define BSLOT     32768       // one weight chunk slot
#define SM_H0     65536
#define SM_H1     (SM_H0 + 66560)
#define SM_MBAR   (SM_H1 + 66560)
#define SM_TOTAL  (SM_MBAR + 64)

#define NCHUNKS 42            // 2 (L1) + 16 (L2) + 16 (L3) + 8 (L4)

// ---------------- device scratch ----------------
__device__ float g_dyn[(size_t)E_ * B_ * D_];
__device__ float g_b1eff[E_ * H_];
// K=32 chunks (512 rows x 64B) for L1..L3; K=64 chunks (64 rows x 128B) for L4
__device__ __align__(128) char g_w1s[E_ * 2 * 32768];
__device__ __align__(128) char g_w2s[(size_t)E_ * 16 * 32768];
__device__ __align__(128) char g_w3s[(size_t)E_ * 16 * 32768];
__device__ __align__(128) char g_w4s[E_ * 8 * 8192];

// ---------------- low-level helpers ----------------
__device__ __forceinline__ uint32_t smem_u32(const void* p) {
    uint32_t a;
    asm("{ .reg .u64 t; cvta.to.shared.u64 t, %1; cvt.u32.u64 %0, t; }" : "=r"(a) : "l"(p));
    return a;
}
__device__ __forceinline__ void ldsm4(uint32_t* r, const void* p) {
    asm volatile("ldmatrix.sync.aligned.m8n8.x4.shared.b16 {%0,%1,%2,%3}, [%4];"
        : "=r"(r[0]), "=r"(r[1]), "=r"(r[2]), "=r"(r[3]) : "r"(smem_u32(p)));
}
__device__ __forceinline__ void ldsm2(uint32_t& r0, uint32_t& r1, const void* p) {
    asm volatile("ldmatrix.sync.aligned.m8n8.x2.shared.b16 {%0,%1}, [%2];"
        : "=r"(r0), "=r"(r1) : "r"(smem_u32(p)));
}
__device__ __forceinline__ void mma16816(float* c, const uint32_t* a, uint32_t b0, uint32_t b1) {
    asm volatile(
        "mma.sync.aligned.m16n8k16.row.col.f32.f16.f16.f32 "
        "{%0,%1,%2,%3}, {%4,%5,%6,%7}, {%8,%9}, {%0,%1,%2,%3};"
        : "+f"(c[0]), "+f"(c[1]), "+f"(c[2]), "+f"(c[3])
        : "r"(a[0]), "r"(a[1]), "r"(a[2]), "r"(a[3]), "r"(b0), "r"(b1));
}
__device__ __forceinline__ void mbar_init(uint32_t a, uint32_t c) {
    asm volatile("mbarrier.init.shared.b64 [%0], %1;" :: "r"(a), "r"(c) : "memory");
}
__device__ __forceinline__ void mbar_arrive(uint32_t a) {
    asm volatile("mbarrier.arrive.shared.b64 _, [%0];" :: "r"(a) : "memory");
}
__device__ __forceinline__ void mbar_expect_tx(uint32_t a, uint32_t bytes) {
    asm volatile("mbarrier.arrive.expect_tx.shared.b64 _, [%0], %1;" :: "r"(a), "r"(bytes) : "memory");
}
__device__ __forceinline__ void bulk_g2s(uint32_t sdst, const void* gsrc, uint32_t bytes, uint32_t mbar) {
    asm volatile(
        "cp.async.bulk.shared::cluster.global.mbarrier::complete_tx::bytes [%0], [%1], %2, [%3];"
        :: "r"(sdst), "l"(gsrc), "r"(bytes), "r"(mbar) : "memory");
}
__device__ __forceinline__ void mbar_wait(uint32_t mbar, uint32_t parity) {
    uint32_t done;
    asm volatile(
        "{ .reg .pred p; mbarrier.try_wait.parity.acquire.cta.shared::cta.b64 p, [%1], %2; selp.b32 %0, 1, 0, p; }"
        : "=r"(done) : "r"(mbar), "r"(parity) : "memory");
    if (!done) {
        asm volatile(
            "{ .reg .pred P1;\n"
            "W_%=:\n\t"
            "mbarrier.try_wait.parity.acquire.cta.shared::cta.b64 P1, [%0], %1, 0x989680;\n\t"
            "@P1 bra.uni D_%=;\n\t"
            "bra.uni W_%=;\n"
            "D_%=: }"
            :: "r"(mbar), "r"(parity) : "memory");
    }
}
// MUFU.TANH (sm_75+ base feature)
__device__ __forceinline__ float tanh_fast(float x) {
    float y;
    asm("tanh.approx.f32 %0, %1;" : "=f"(y) : "f"(x));
    return y;
}

// ---------------- weight prep ----------------
// L1-L3 chunk layout: K=32 chunk, row n (0..511), 16B unit j (0..3):
//   phys = (n>>1)*128 + (n&1)*64 + ((j ^ ((n>>1)&3)) << 4)
__global__ void conv_small(const float* __restrict__ W1, const float* __restrict__ W4,
                           const float* __restrict__ b1, const float* __restrict__ t,
                           const float* __restrict__ omega)
{
    int i = blockIdx.x * blockDim.x + threadIdx.x;
    if (i < 131072) {
        // W1[:, :64]: E*512 rows x 32 k-pairs -> 2 K32 chunks/expert
        int e = i >> 14, r = i & 16383;
        int n = r >> 5, k = (r & 31) * 2;
        int kc = k >> 5, kl = k & 31, j = kl >> 3;
        size_t chunk = (size_t)(e * 2 + kc) * 32768;
        uint32_t off = (uint32_t)((n >> 1) * 128 + (n & 1) * 64
                     + ((j ^ ((n >> 1) & 3)) << 4) + (kl & 7) * 2);
        const float* s = W1 + ((size_t)e * 512 + n) * IN_RAW + k;
        *(__half2*)(g_w1s + chunk + off) = __floats2half2_rn(s[0], s[1]);
    } else if (i < 262144) {
        // W4: E*64 rows x 256 k-pairs -> 8 K64 chunks/expert (old 128B-row layout)
        int jj = i - 131072;
        int e = jj >> 14, r = jj & 16383;
        int n = r >> 8, k = (r & 255) * 2;
        int kc = k >> 6, kl = k & 63;
        size_t chunk = ((size_t)e * 8 + kc) * 8192;
        uint32_t off = (uint32_t)(n * 128) + (((uint32_t)(kl * 2)) ^ ((uint32_t)(n & 7) << 4));
        const float* s = W4 + ((size_t)e * 64 + n) * 512 + k;
        *(__half2*)(g_w4s + chunk + off) = __floats2half2_rn(s[0], s[1]);
    } else if (i < 262144 + E_ * H_) {
        int jj = i - 262144;
        int e = jj >> 9;
        float tv = t[0], om = omega[e];
        const float* w = W1 + (size_t)jj * IN_RAW;
        g_b1eff[jj] = b1[jj] + tv * w[64] + sinf(om * tv) * w[65] + cosf(om * tv) * w[66];
    }
}
__global__ void conv_w23s(const float* __restrict__ W, char* __restrict__ dst) {
    int i = blockIdx.x * blockDim.x + threadIdx.x;     // E*512*256 k-pairs
    int e = i >> 17, r = i & 131071;
    int n = r >> 8, k = (r & 255) * 2;
    int kc = k >> 5, kl = k & 31, j = kl >> 3;
    size_t chunk = ((size_t)(e * 16 + kc)) * 32768;
    uint32_t off = (uint32_t)((n >> 1) * 128 + (n & 1) * 64
                 + ((j ^ ((n >> 1) & 3)) << 4) + (kl & 7) * 2);
    const float* s = W + ((size_t)e * 512 + n) * 512 + k;
    *(__half2*)(dst + chunk + off) = __floats2half2_rn(s[0], s[1]);
}

// ---------------- chunk stream ----------------
struct Stream {
    uint32_t fullb[2], emptyb[2], bdst[2];
    int pc[2], cc[2];
    int gp, gc;
    bool leader;
    const char *w1b, *w2b, *w3b, *w4b;
};
__device__ __forceinline__ void produce_next(Stream& s) {
    int i = s.gp;
    if (i >= NCHUNKS) return;
    const char* p;
    uint32_t bytes;
    if (i < 2)       { p = s.w1b + (size_t)i * 32768;        bytes = 32768; }
    else if (i < 18) { p = s.w2b + (size_t)(i - 2) * 32768;  bytes = 32768; }
    else if (i < 34) { p = s.w3b + (size_t)(i - 18) * 32768; bytes = 32768; }
    else             { p = s.w4b + (size_t)(i - 34) * 8192;  bytes = 8192;  }
    int b = i & 1;
    if (s.leader) {
        if (s.pc[b] > 0) mbar_wait(s.emptyb[b], (uint32_t)((s.pc[b] - 1) & 1));
        mbar_expect_tx(s.fullb[b], bytes);
        bulk_g2s(s.bdst[b], p, bytes, s.fullb[b]);
    }
    s.pc[b]++; s.gp++;
}
__device__ __forceinline__ int consume_wait(Stream& s) {
    int b = s.gc & 1;
    mbar_wait(s.fullb[b], (uint32_t)(s.cc[b] & 1));
    return b;
}
__device__ __forceinline__ void consume_done(Stream& s, bool wl) {
    int b = s.gc & 1;
    if (wl) mbar_arrive(s.emptyb[b]);
    s.cc[b]++; s.gc++;
}

// ---------------- single N=512 pass (layers 1-3), warp tile 32x64 ----------------
__device__ __forceinline__ void run_pass512(Stream& S, char* smc,
        const __half* __restrict__ hin, __half* __restrict__ hout,
        int nch, const float* __restrict__ bias, int warp, int lane)
{
    const int mg = warp >> 3, ng = warp & 7;
    const bool wl = (lane == 0);
    const int g = lane >> 3, lr = lane & 7;
    const int arow = mg * 32 + (lane & 15);
    const int acol = (lane >> 4) << 3;
    const int nbase = ng * 64 + ((g >> 1) << 3) + lr;
    const int jpar = g & 1;

    float acc[2][8][4];
    #pragma unroll
    for (int mt = 0; mt < 2; mt++)
        #pragma unroll
        for (int nt = 0; nt < 8; nt++)
            #pragma unroll
            for (int i = 0; i < 4; i++) acc[mt][nt][i] = 0.0f;

    #pragma unroll 1
    for (int kc = 0; kc < nch; kc++) {
        int b = consume_wait(S);
        const char* wb = smc + b * BSLOT;
        #pragma unroll
        for (int ks = 0; ks < 2; ks++) {
            const int kk = kc * 32 + ks * 16;
            uint32_t a[2][4];
            ldsm4(a[0], hin + arow * HSTR + kk + acol);
            ldsm4(a[1], hin + (arow + 16) * HSTR + kk + acol);
            const int j = ks * 2 + jpar;
            #pragma unroll
            for (int nt4 = 0; nt4 < 4; nt4++) {
                const int nrow = nbase + nt4 * 16;
                const char* p = wb + (uint32_t)((nrow >> 1) * 128 + (nrow & 1) * 64
                               + ((j ^ ((nrow >> 1) & 3)) << 4));
                uint32_t bb[4];
                ldsm4(bb, p);
                mma16816(acc[0][2 * nt4],     a[0], bb[0], bb[1]);
                mma16816(acc[1][2 * nt4],     a[1], bb[0], bb[1]);
                mma16816(acc[0][2 * nt4 + 1], a[0], bb[2], bb[3]);
                mma16816(acc[1][2 * nt4 + 1], a[1], bb[2], bb[3]);
            }
        }
        consume_done(S, wl);
        produce_next(S);
    }

    // epilogue: tanh(acc + bias) -> hout fp16
    #pragma unroll
    for (int mt = 0; mt < 2; mt++) {
        #pragma unroll
        for (int nt = 0; nt < 8; nt++) {
            const int cb = ng * 64 + nt * 8 + (lane & 3) * 2;
            const float2 bb = *(const float2*)(bias + cb);
            const int r0 = mg * 32 + mt * 16 + (lane >> 2);
            float v0 = tanh_fast(acc[mt][nt][0] + bb.x);
            float v1 = tanh_fast(acc[mt][nt][1] + bb.y);
            float v2 = tanh_fast(acc[mt][nt][2] + bb.x);
            float v3 = tanh_fast(acc[mt][nt][3] + bb.y);
            *(__half2*)(hout + r0 * HSTR + cb)       = __floats2half2_rn(v0, v1);
            *(__half2*)(hout + (r0 + 8) * HSTR + cb) = __floats2half2_rn(v2, v3);
        }
    }
}

// ---------------- layer 4: N=64, K=64 chunks, fp32 out ----------------
__device__ __forceinline__ void run_pass64(Stream& S, char* smc,
        const __half* __restrict__ hin, float* __restrict__ dynout,
        int nch, const float* __restrict__ bias, int warp, int lane)
{
    const int mg = warp >> 3, ng = warp & 7;
    const bool wl = (lane == 0);
    const int g = lane >> 3, lr = lane & 7;
    const int arow = mg * 32 + (lane & 15);
    const int acol = (lane >> 4) << 3;

    float acc[2][4];
    #pragma unroll
    for (int mt = 0; mt < 2; mt++)
        #pragma unroll
        for (int i = 0; i < 4; i++) acc[mt][i] = 0.0f;

    #pragma unroll 1
    for (int kc = 0; kc < nch; kc++) {
        int b = consume_wait(S);
        const char* wb = smc + b * BSLOT;
        #pragma unroll
        for (int ks = 0; ks < 4; ks++) {
            const int kk = kc * 64 + ks * 16;
            uint32_t a[2][4];
            ldsm4(a[0], hin + arow * HSTR + kk + acol);
            ldsm4(a[1], hin + (arow + 16) * HSTR + kk + acol);
            const int nrow = ng * 8 + lr;
            const uint32_t j = (uint32_t)(ks * 2 + (g & 1));
            const char* p = wb + nrow * 128 + ((j << 4) ^ ((uint32_t)(nrow & 7) << 4));
            uint32_t b0, b1;
            ldsm2(b0, b1, p);
            mma16816(acc[0], a[0], b0, b1);
            mma16816(acc[1], a[1], b0, b1);
        }
        consume_done(S, wl);
        produce_next(S);
    }

    const int cb = ng * 8 + (lane & 3) * 2;
    const float2 bb = *(const float2*)(bias + cb);
    #pragma unroll
    for (int mt = 0; mt < 2; mt++) {
        const int r0 = mg * 32 + mt * 16 + (lane >> 2);
        float2 f01; f01.x = acc[mt][0] + bb.x; f01.y = acc[mt][1] + bb.y;
        float2 f23; f23.x = acc[mt][2] + bb.x; f23.y = acc[mt][3] + bb.y;
        *(float2*)(dynout + (size_t)r0 * D_ + cb)       = f01;
        *(float2*)(dynout + (size_t)(r0 + 8) * D_ + cb) = f23;
    }
}

// ---------------- fused per-tile, per-expert MLP kernel ----------------
__global__ __launch_bounds__(THREADS, 1)
void mlp_kernel(const float* __restrict__ x,
                const float* __restrict__ b2, const float* __restrict__ b3,
                const float* __restrict__ b4)
{
    extern __shared__ __align__(1024) char smc[];
    __half* h0 = (__half*)(smc + SM_H0);
    __half* h1 = (__half*)(smc + SM_H1);
    const uint32_t mb = smem_u32(smc + SM_MBAR);

    const int tid  = threadIdx.x;
    const int warp = tid >> 5, lane = tid & 31;
    const int e    = blockIdx.y;
    const int row0 = blockIdx.x * BM;

    Stream S;
    S.fullb[0] = mb; S.fullb[1] = mb + 8;
    S.emptyb[0] = mb + 16; S.emptyb[1] = mb + 24;
    S.bdst[0] = smem_u32(smc); S.bdst[1] = smem_u32(smc + BSLOT);
    S.pc[0] = S.pc[1] = S.cc[0] = S.cc[1] = 0;
    S.gp = S.gc = 0;
    S.leader = (tid == 0);
    S.w1b = g_w1s + (size_t)e * 2 * 32768;
    S.w2b = g_w2s + (size_t)e * 16 * 32768;
    S.w3b = g_w3s + (size_t)e * 16 * 32768;
    S.w4b = g_w4s + (size_t)e * 8 * 8192;

    if (tid == 0) {
        mbar_init(S.fullb[0], 1);  mbar_init(S.fullb[1], 1);
        mbar_init(S.emptyb[0], 16); mbar_init(S.emptyb[1], 16);
        asm volatile("fence.proxy.async.shared::cta;" ::: "memory");
    }
    __syncthreads();

    produce_next(S);
    produce_next(S);

    // layer-1 A tile: just x (trig terms folded into g_b1eff)
    for (int idx = tid; idx < BM * 64; idx += THREADS) {
        int r = idx >> 6, c = idx & 63;
        h0[r * HSTR + c] = __float2half(x[(size_t)(row0 + r) * 64 + c]);
    }
    __syncthreads();

    float* dyn = g_dyn + ((size_t)e * B_ + row0) * D_;

    run_pass512(S, smc, h0, h1, 2,  g_b1eff + e * H_, warp, lane);
    __syncthreads();
    run_pass512(S, smc, h1, h0, 16, b2 + e * H_,      warp, lane);
    __syncthreads();
    run_pass512(S, smc, h0, h1, 16, b3 + e * H_,      warp, lane);
    __syncthreads();
    run_pass64 (S, smc, h1, dyn, 8, b4 + e * D_,      warp, lane);
}

// ---------------- expert-weighted combine (deterministic) ----------------
__global__ void combine_k(const float* __restrict__ ew, float* __restrict__ out)
{
    int i = blockIdx.x * blockDim.x + threadIdx.x;
    int b = i >> 6;
    float s = 0.0f;
    #pragma unroll
    for (int e = 0; e < E_; e++)
        s += ew[b * E_ + e] * g_dyn[(size_t)e * B_ * D_ + i];
    out[i] = s;
}

// ---------------- launch ----------------
extern "C" void kernel_launch(void* const* d_in, const int* in_sizes, int n_in,
                              void* d_out, int out_size)
{
    const float* t  = (const float*)d_in[0];
    const float* x  = (const float*)d_in[1];
    const float* ew = (const float*)d_in[2];
    const float* om = (const float*)d_in[3];
    const float* W1 = (const float*)d_in[4];
    const float* b1 = (const float*)d_in[5];
    const float* W2 = (const float*)d_in[6];
    const float* b2 = (const float*)d_in[7];
    const float* W3 = (const float*)d_in[8];
    const float* b3 = (const float*)d_in[9];
    const float* W4 = (const float*)d_in[10];
    const float* b4 = (const float*)d_in[11];
    float* out = (float*)d_out;

    cudaFuncSetAttribute(mlp_kernel, cudaFuncAttributeMaxDynamicSharedMemorySize, SM_TOTAL);

    char* w2s_ptr = nullptr;
    char* w3s_ptr = nullptr;
    cudaGetSymbolAddress((void**)&w2s_ptr, g_w2s);
    cudaGetSymbolAddress((void**)&w3s_ptr, g_w3s);

    // launch order keeps mlp_kernel as the ncu capture target
    conv_small<<<(262144 + E_ * H_ + 255) / 256, 256>>>(W1, W4, b1, t, om);
    conv_w23s<<<(E_ * 512 * 256) / 256, 256>>>(W2, w2s_ptr);
    conv_w23s<<<(E_ * 512 * 256) / 256, 256>>>(W3, w3s_ptr);

    dim3 grid(B_ / BM, E_);
    mlp_kernel<<<grid, THREADS, SM_TOTAL>>>(x, b2, b3, b4);

    combine_k<<<(B_ * D_) / 256, 256>>>(ew, out);
}